// round 5
// baseline (speedup 1.0000x reference)
#include <cuda_runtime.h>
#include <math.h>

// Toeplitz identity:
//   out[m,n] = sum_j P_j*cos((m-n)*f_j) + Q_j*sin((m-n)*f_j)
// so only 2c-1 distinct values exist. Build g once, broadcast-fill output.

// Scratch table for g(d), d = i - (c-1). Sized for c up to 16384.
__device__ float g_table[32768];

__global__ void compute_g_kernel(const float* __restrict__ a,
                                 const float* __restrict__ b,
                                 int c) {
    __shared__ float  Psh[64];
    __shared__ float  Qsh[64];
    __shared__ double Fsh[64];

    const int t = threadIdx.x;
    if (t < 64) {
        float a1 = a[t], a2 = a[t + 64];
        float b1 = b[t], b2 = b[t + 64];
        Psh[t] = a1 * b1 + a2 * b2;
        Qsh[t] = a1 * b2 - a2 * b1;
        // inv_freq[j] = 10000^(-j/64) = exp(-j * ln(10000)/64), in double
        Fsh[t] = exp(-(double)t * 0.14391156831212785);
    }
    __syncthreads();

    const int i = blockIdx.x * blockDim.x + t;
    if (i >= 2 * c - 1) return;

    const double d = (double)(i - (c - 1));

    float acc = 0.0f;
    const double inv2pi = 0.15915494309189535;
    const double twopi  = 6.283185307179586;
#pragma unroll 8
    for (int j = 0; j < 64; j++) {
        double ang = d * Fsh[j];
        // range-reduce in double so fast-math sincosf stays accurate
        double k = rint(ang * inv2pi);
        float  r = (float)(ang - k * twopi);
        float s, co;
        sincosf(r, &s, &co);
        acc += Psh[j] * co + Qsh[j] * s;
    }
    g_table[i] = acc;
}

// out[m][n] = g_table[(c-1) + m - n]; each thread writes one float4.
// blockIdx.y = row m (no integer division), blockIdx.x covers columns.
__global__ void fill_kernel(float4* __restrict__ out, int c) {
    const int m    = blockIdx.y;
    const int col4 = blockIdx.x * blockDim.x + threadIdx.x;
    const int n    = col4 << 2;
    const int base = (c - 1) + m - n;   // descending along n

    float4 v;
    v.x = g_table[base];
    v.y = g_table[base - 1];
    v.z = g_table[base - 2];
    v.w = g_table[base - 3];

    out[(size_t)m * (size_t)(c >> 2) + (size_t)col4] = v;
}

extern "C" void kernel_launch(void* const* d_in, const int* in_sizes, int n_in,
                              void* d_out, int out_size) {
    const float* a = (const float*)d_in[0];
    const float* b = (const float*)d_in[1];
    // c is the side length of the square output: out_size = c*c
    int c = (int)(sqrt((double)out_size) + 0.5);

    // Kernel A: build the (2c-1)-entry Toeplitz generator table
    {
        int total  = 2 * c - 1;
        int blocks = (total + 255) / 256;
        compute_g_kernel<<<blocks, 256>>>(a, b, c);
    }

    // Kernel B: broadcast-fill the c x c output, float4 stores
    {
        dim3 grid((c / 4 + 255) / 256, c);
        fill_kernel<<<grid, 256>>>((float4*)d_out, c);
    }
}

// round 6
// speedup vs baseline: 1.2474x; 1.2474x over previous
#include <cuda_runtime.h>
#include <math.h>

// out[m,n] = rope(a,m) . rope(b,n) depends only on (m-n):
//   out[m,n] = sum_j P_j*cos((m-n)*f_j) + Q_j*sin((m-n)*f_j)
// Build g(d) once (2c-1 values), then Toeplitz broadcast-fill.

__device__ float g_table[32768];

// ---------------- Kernel A: generator table, warp-per-i ----------------
__global__ void compute_g_kernel(const float* __restrict__ a,
                                 const float* __restrict__ b,
                                 int c) {
    __shared__ float  Psh[64];
    __shared__ float  Qsh[64];
    __shared__ double Fsh[64];

    const int t = threadIdx.x;
    if (t < 64) {
        float a1 = a[t], a2 = a[t + 64];
        float b1 = b[t], b2 = b[t + 64];
        Psh[t] = a1 * b1 + a2 * b2;
        Qsh[t] = a1 * b2 - a2 * b1;
        // inv_freq[j] = 10000^(-j/64) = exp(-j * ln(10000)/64)
        Fsh[t] = exp(-(double)t * 0.14391156831212785);
    }
    __syncthreads();

    const int lane = t & 31;
    const int i    = blockIdx.x * (blockDim.x >> 5) + (t >> 5);
    if (i >= 2 * c - 1) return;

    const double d      = (double)(i - (c - 1));
    const double inv2pi = 0.15915494309189535;
    const double twopi  = 6.283185307179586;

    float acc = 0.0f;
#pragma unroll
    for (int jj = 0; jj < 2; jj++) {
        int j = lane + jj * 32;
        double ang = d * Fsh[j];
        double k   = rint(ang * inv2pi);       // double range reduction
        float  r   = (float)(ang - k * twopi); // safe for fast-math sincosf
        float s, co;
        sincosf(r, &s, &co);
        acc += Psh[j] * co + Qsh[j] * s;
    }
#pragma unroll
    for (int o = 16; o; o >>= 1)
        acc += __shfl_xor_sync(0xFFFFFFFFu, acc, o);

    if (lane == 0) g_table[i] = acc;
}

// ---------------- Kernel B: Toeplitz fill via smem staging ----------------
// Tile: ROWS x 1024 per block (256 threads, one float4-column per thread).
// Reversed slice rsm0[k] = g[hi-k] is stored in 4 shift-copies so every
// (row, col4) access is an aligned, conflict-free LDS.128.
#define TROWS   32
#define TCOLS   1024
#define KLEN    (TCOLS + TROWS - 1)     // 1055 used indices
#define SSTRIDE 1060                    // float stride per copy (16B-mult)

__global__ void __launch_bounds__(256) fill_kernel(float4* __restrict__ out, int c) {
    __shared__ float rsm[4 * SSTRIDE];

    const int t  = threadIdx.x;
    const int m0 = blockIdx.y * TROWS;
    const int n0 = blockIdx.x * TCOLS;

    // base0 = g-index of out[m0][n0]; hi = max g-index this tile touches
    const int base0 = (c - 1) + m0 - n0;
    const int hi    = base0 + TROWS - 1;
    const int gmax  = 2 * c - 2;

    // Fill 4 shifted reversed copies: copy_s[k] = g[hi - k - s]
#pragma unroll
    for (int s = 0; s < 4; s++) {
        for (int k = t; k < KLEN; k += 256) {
            int gi = hi - k - s;
            float v = (gi >= 0 && gi <= gmax) ? g_table[gi] : 0.0f;
            rsm[s * SSTRIDE + k] = v;
        }
    }
    __syncthreads();

    const int cq = c >> 2;
    float4* orow = out + (size_t)m0 * (size_t)cq + (n0 >> 2) + t;

    // row r, column 4t+e  ->  g[base0 + r - 4t - e] = rsm0[x + 4t + e],
    // x = TROWS-1-r.  With s = x&3: aligned float4 at copy_s[(x-s) + 4t].
#pragma unroll
    for (int r = 0; r < TROWS; r++) {
        const int x = TROWS - 1 - r;
        const int s = x & 3;                      // compile-time per r
        const float4* src =
            (const float4*)(rsm + s * SSTRIDE + (x - s)) + t;
        orow[(size_t)r * (size_t)cq] = *src;
    }
}

extern "C" void kernel_launch(void* const* d_in, const int* in_sizes, int n_in,
                              void* d_out, int out_size) {
    const float* a = (const float*)d_in[0];
    const float* b = (const float*)d_in[1];
    int c = (int)(sqrt((double)out_size) + 0.5);   // out is c x c

    // Kernel A: (2c-1) g-values, one warp each, 8 warps/block
    {
        int total  = 2 * c - 1;
        int blocks = (total + 7) / 8;
        compute_g_kernel<<<blocks, 256>>>(a, b, c);
    }

    // Kernel B: tiled broadcast fill
    {
        dim3 grid(c / TCOLS, c / TROWS);
        fill_kernel<<<grid, 256>>>((float4*)d_out, c);
    }
}

// round 7
// speedup vs baseline: 1.3855x; 1.1107x over previous
#include <cuda_runtime.h>
#include <math.h>

// out[m,n] = rope(a,m) . rope(b,n) depends only on (m-n):
//   out[m,n] = sum_j P_j*cos((m-n)*f_j) + Q_j*sin((m-n)*f_j)
// Build g(d) once (2c-1 values), then Toeplitz broadcast-fill.

__device__ float g_table[32768];

// ---------------- Kernel A: generator table ----------------
// One warp produces BOTH g(+d) and g(-d) from one sincos pass:
//   g(+d) = sum P*cos + Q*sin ,  g(-d) = sum P*cos - Q*sin
__global__ void __launch_bounds__(512) compute_g_kernel(
        const float* __restrict__ a,
        const float* __restrict__ b,
        int c) {
    __shared__ float  Psh[64];
    __shared__ float  Qsh[64];
    __shared__ double Fsh[64];

    const int t = threadIdx.x;
    if (t < 64) {
        float a1 = a[t], a2 = a[t + 64];
        float b1 = b[t], b2 = b[t + 64];
        Psh[t] = a1 * b1 + a2 * b2;
        Qsh[t] = a1 * b2 - a2 * b1;
        // inv_freq[j] = 10000^(-j/64) = exp(-j * ln(10000)/64)
        Fsh[t] = exp(-(double)t * 0.14391156831212785);
    }
    __syncthreads();

    const int lane = t & 31;
    const int i    = blockIdx.x * (blockDim.x >> 5) + (t >> 5);  // d = i
    if (i >= c) return;

    const double d      = (double)i;
    const double inv2pi = 0.15915494309189535;
    const double twopi  = 6.283185307179586;

    float accP = 0.0f, accQ = 0.0f;
#pragma unroll
    for (int jj = 0; jj < 2; jj++) {
        int j = lane + jj * 32;
        double ang = d * Fsh[j];
        double k   = rint(ang * inv2pi);       // double range reduction
        float  r   = (float)(ang - k * twopi); // safe for fast-math sincosf
        float s, co;
        sincosf(r, &s, &co);
        accP += Psh[j] * co;
        accQ += Qsh[j] * s;
    }
#pragma unroll
    for (int o = 16; o; o >>= 1) {
        accP += __shfl_xor_sync(0xFFFFFFFFu, accP, o);
        accQ += __shfl_xor_sync(0xFFFFFFFFu, accQ, o);
    }

    if (lane == 0) {
        g_table[(c - 1) + i] = accP + accQ;   // g(+d)
        g_table[(c - 1) - i] = accP - accQ;   // g(-d)
    }
}

// ---------------- Kernel B: Toeplitz fill via smem staging ----------------
// Tile: 64 x 1024 per block (256 threads, one float4-column per thread).
// Reversed slice rsm0[k] = g[hi-k] stored in 4 shift-copies so every
// (row, col4) access is an aligned, conflict-free LDS.128.
#define TROWS   64
#define TCOLS   1024
#define KLEN    (TCOLS + TROWS - 1)     // 1087 used indices
#define SSTRIDE 1092                    // float stride per copy (16B-mult)

__global__ void __launch_bounds__(256) fill_kernel(float4* __restrict__ out, int c) {
    __shared__ float rsm[4 * SSTRIDE];

    const int t  = threadIdx.x;
    const int m0 = blockIdx.y * TROWS;
    const int n0 = blockIdx.x * TCOLS;

    // base0 = g-index of out[m0][n0]; hi = max g-index this tile touches
    const int base0 = (c - 1) + m0 - n0;
    const int hi    = base0 + TROWS - 1;
    const int gmax  = 2 * c - 2;

    // Fill 4 shifted reversed copies: copy_s[k] = g[hi - k - s]
#pragma unroll
    for (int s = 0; s < 4; s++) {
        for (int k = t; k < KLEN; k += 256) {
            int gi = hi - k - s;
            float v = (gi >= 0 && gi <= gmax) ? g_table[gi] : 0.0f;
            rsm[s * SSTRIDE + k] = v;
        }
    }
    __syncthreads();

    const int cq = c >> 2;
    float4* orow = out + (size_t)m0 * (size_t)cq + (n0 >> 2) + t;

    // row r, column 4t+e  ->  g[base0 + r - 4t - e] = rsm0[x + 4t + e],
    // x = TROWS-1-r.  With s = x&3: aligned float4 at copy_s[(x-s) + 4t].
#pragma unroll
    for (int r = 0; r < TROWS; r++) {
        const int x = TROWS - 1 - r;
        const int s = x & 3;                      // compile-time per r
        const float4* src =
            (const float4*)(rsm + s * SSTRIDE + (x - s)) + t;
        __stcs(orow + (size_t)r * (size_t)cq, *src);   // streaming store
    }
}

extern "C" void kernel_launch(void* const* d_in, const int* in_sizes, int n_in,
                              void* d_out, int out_size) {
    const float* a = (const float*)d_in[0];
    const float* b = (const float*)d_in[1];
    int c = (int)(sqrt((double)out_size) + 0.5);   // out is c x c

    // Kernel A: c warp-pairs (each writes g(+d) and g(-d)), 16 warps/block
    {
        int blocks = (c + 15) / 16;
        compute_g_kernel<<<blocks, 512>>>(a, b, c);
    }

    // Kernel B: tiled broadcast fill, single wave (1024 blocks for c=8192)
    {
        dim3 grid(c / TCOLS, c / TROWS);
        fill_kernel<<<grid, 256>>>((float4*)d_out, c);
    }
}